// round 16
// baseline (speedup 1.0000x reference)
#include <cuda_runtime.h>
#include <cuda_bf16.h>
#include <math.h>

#define TT 128
#define BB 256
#define DD 128
#define LL 32
#define CC 64
#define HH 256
#define SS 16
#define SB 4096   // SS*BB

#define DTV 0.02f
#define SQDT 0.14142135623730951f     // sqrt(0.02)
#define LOGDT -3.9120230054281460f    // log(0.02)

// g-table: values only, z in [-24,24], step 1/128
#define NPT 6145
#define TSTRIDE 6208
#define INVDZ 128.0f
#define ZOFF 3072.0f
#define ZLO -24.0f

// euler geometry: 128 blocks x 512 threads, 32 rows/block, 1 block/SM
#define ERPB 32      // rows per block
#define ESTR 36      // smem activation stride (floats; 144B = 16B-aligned rows)
#define ETHR 512

typedef unsigned long long ull;

// ---------------- device scratch ----------------
static __device__ float g_WihT[DD*768];
static __device__ float g_WhhT[HH*768];
static __device__ float g_encWt[HH*CC];
static __device__ float g_fW1n[96*HH];     // non-dup, k-major: [c*256+n]
static __device__ float g_fW2n[HH*HH];
static __device__ float g_hW1n[LL*HH];
static __device__ float g_hW2n[HH*HH];
static __device__ float g_fW3t[HH*LL];     // k-major non-dup: [kk*32+l]
static __device__ float g_hW3t[HH*LL];
static __device__ float g_gi[TT*BB*768];
static __device__ float g_hs[TT*BB*HH];
static __device__ float g_ctx[TT*BB*CC];
static __device__ float g_logqp[SB];
static __device__ double g_acc[2];
static __device__ int    g_gcnt[32];
static __device__ float  g_tabv[32*TSTRIDE];

__device__ __forceinline__ float sigm_(float x){ return 1.f/(1.f+__expf(-x)); }

// softplus: 1 MUFU (ex2.approx) + FMA-pipe log polynomial (Cephes logf range)
__device__ __forceinline__ float splus_(float x){
    float t = -fabsf(x)*1.4426950408889634f;   // -|x| * log2(e)
    float u;
    asm("ex2.approx.f32 %0, %1;" : "=f"(u) : "f"(t));   // u = 2^t = exp(-|x|), in (0,1]
    float v = 1.f + u;                          // [1,2]
    bool big = v > 1.41421356f;
    float zv = big ? v*0.5f : v;
    float ladd = big ? 0.69314718056f : 0.f;
    float z = zv - 1.f;                         // in [-0.2929, 0.4142]
    float P = 7.0376836292E-2f;
    P = fmaf(P, z, -1.1514610310E-1f);
    P = fmaf(P, z,  1.1676998740E-1f);
    P = fmaf(P, z, -1.2420140846E-1f);
    P = fmaf(P, z,  1.4249322787E-1f);
    P = fmaf(P, z, -1.6668057665E-1f);
    P = fmaf(P, z,  2.0000714765E-1f);
    P = fmaf(P, z, -2.4999993993E-1f);
    P = fmaf(P, z,  3.3333331174E-1f);
    float z2 = z*z;
    float lnv = fmaf(z2*z, P, fmaf(-0.5f, z2, z)) + ladd;
    return fmaxf(x,0.f) + lnv;
}
__device__ __forceinline__ ull pack2(float x, float y){
    ull r; asm("mov.b64 %0, {%1,%2};" : "=l"(r) : "f"(x), "f"(y)); return r;
}
__device__ __forceinline__ ull fma2(ull a, ull b, ull c){
    ull d; asm("fma.rn.f32x2 %0, %1, %2, %3;" : "=l"(d) : "l"(a), "l"(b), "l"(c)); return d;
}
__device__ __forceinline__ float2 unpack2(ull v){
    float2 f; asm("mov.b64 {%0,%1}, %2;" : "=f"(f.x), "=f"(f.y) : "l"(v)); return f;
}

// ---------------- prep ----------------
__global__ void prep_kernel(const float* __restrict__ Wih, const float* __restrict__ Whh,
                            const float* __restrict__ fW1, const float* __restrict__ fW2,
                            const float* __restrict__ fW3, const float* __restrict__ hW1,
                            const float* __restrict__ hW2, const float* __restrict__ hW3,
                            const float* __restrict__ encW){
    int i = blockIdx.x*blockDim.x + threadIdx.x;
    int nth = gridDim.x*blockDim.x;
    for (int k=i;k<SB;k+=nth)    g_logqp[k]=0.f;
    if (i<2) g_acc[i]=0.0;
    if (i<32) g_gcnt[i]=0;
    for (int k=i;k<768*DD;k+=nth){int n=k/DD,d=k%DD; g_WihT[d*768+n]=Wih[k];}
    for (int k=i;k<768*HH;k+=nth){int n=k/HH,d=k%HH; g_WhhT[d*768+n]=Whh[k];}
    for (int k=i;k<CC*HH;k+=nth){int c2=k/HH,kk=k%HH;g_encWt[kk*CC+c2]=encW[k];}
    for (int k=i;k<HH*96;k+=nth){int n=k/96,c=k%96;  g_fW1n[c*HH+n]=fW1[k];}
    for (int k=i;k<HH*HH;k+=nth){int n=k/HH,c=k%HH;  g_fW2n[c*HH+n]=fW2[k];}
    for (int k=i;k<HH*LL;k+=nth){int n=k/LL,c=k%LL;  g_hW1n[c*HH+n]=hW1[k];}
    for (int k=i;k<HH*HH;k+=nth){int n=k/HH,c=k%HH;  g_hW2n[c*HH+n]=hW2[k];}
    for (int k=i;k<LL*HH;k+=nth){int l=k/HH,kk=k%HH;
        g_fW3t[kk*LL+l]=fW3[k]; g_hW3t[kk*LL+l]=hW3[k];}
}

// ---------------- g-table build ----------------
__global__ void tabv_kernel(const float* __restrict__ gW1,const float* __restrict__ gb1,
                            const float* __restrict__ gW2,const float* __restrict__ gb2){
    __shared__ float w1[HH], b1[HH], w2[HH];
    int l = blockIdx.y;
    int tid = threadIdx.x;
    if(tid<HH){ w1[tid]=gW1[l*HH+tid]; b1[tid]=gb1[l*HH+tid]; w2[tid]=gW2[l*HH+tid]; }
    __syncthreads();
    int j = blockIdx.x*256 + tid;
    if(j>=NPT) return;
    float z = ZLO + (float)j*(1.0f/INVDZ);
    float acc=0.f;
    #pragma unroll 4
    for(int h=0;h<HH;h++){
        float t = fmaf(z, w1[h], b1[h]);
        acc = fmaf(splus_(t), w2[h], acc);
    }
    g_tabv[l*TSTRIDE+j] = 1.f/(1.f+__expf(-(acc+gb2[l]))) + 0.01f;
}

// ---------------- gi = xs_rev @ WihT + bih ----------------
__global__ void gi_kernel(const float* __restrict__ xs_pre, const float* __restrict__ bih){
    __shared__ float xT[DD*8];
    int tid = threadIdx.x;
    int row0 = blockIdx.x*8;
    for (int e=tid; e<8*DD; e+=256){
        int i=e>>7, k=e&127;
        int rid=row0+i; int t=rid>>8, b=rid&255;
        xT[k*8+i] = xs_pre[(b*TT + (TT-1-t))*DD + k];
    }
    __syncthreads();
    int n0=tid, n1=tid+256, n2=tid+512;
    float a0[8],a1[8],a2[8];
    float b0=bih[n0], b1=bih[n1], b2=bih[n2];
    #pragma unroll
    for(int i=0;i<8;i++){a0[i]=b0;a1[i]=b1;a2[i]=b2;}
    #pragma unroll 2
    for(int k=0;k<DD;k++){
        float w0=g_WihT[k*768+n0], w1=g_WihT[k*768+n1], w2=g_WihT[k*768+n2];
        float4 xa=*(const float4*)&xT[k*8], xb=*(const float4*)&xT[k*8+4];
        float xv[8]={xa.x,xa.y,xa.z,xa.w,xb.x,xb.y,xb.z,xb.w};
        #pragma unroll
        for(int i=0;i<8;i++){a0[i]=fmaf(xv[i],w0,a0[i]);a1[i]=fmaf(xv[i],w1,a1[i]);a2[i]=fmaf(xv[i],w2,a2[i]);}
    }
    for(int i=0;i<8;i++){
        int rid=row0+i;
        g_gi[rid*768+n0]=a0[i]; g_gi[rid*768+n1]=a1[i]; g_gi[rid*768+n2]=a2[i];
    }
}

// ---------------- persistent GRU ----------------
__global__ __launch_bounds__(384,2) void gru_all_kernel(const float* __restrict__ bhh){
    __shared__ float hT[HH*8];
    __shared__ float part[96*4*9];
    int tid = threadIdx.x;
    int bg = blockIdx.x>>3, hg = blockIdx.x&7;
    int b0 = bg*8, hbase = hg*32;
    for(int e=tid;e<8*HH;e+=384) hT[e]=0.f;

    int c  = tid%96;
    int kp = tid/96;
    int gate = c>>5;
    int n = gate*256 + hbase + (c&31);
    int k0 = kp*64;
    const float* wcol = &g_WhhT[(long)k0*768 + n];
    float br=bhh[hbase+(tid&31)], bz=bhh[256+hbase+(tid&31)], bn=bhh[512+hbase+(tid&31)];

    volatile int* cnt = (volatile int*)&g_gcnt[bg];

    for(int t=0;t<TT;t++){
        __syncthreads();
        ull acc0=0ull, acc1=0ull, acc2=0ull, acc3=0ull;
        #pragma unroll 4
        for(int kk=0;kk<64;kk++){
            float w = __ldg(&wcol[(long)kk*768]);
            ull wp = pack2(w,w);
            const ull* hp = (const ull*)&hT[(k0+kk)*8];
            acc0=fma2(hp[0],wp,acc0); acc1=fma2(hp[1],wp,acc1);
            acc2=fma2(hp[2],wp,acc2); acc3=fma2(hp[3],wp,acc3);
        }
        float* pp = &part[(c*4+kp)*9];
        float2 v0=unpack2(acc0), v1=unpack2(acc1), v2=unpack2(acc2), v3=unpack2(acc3);
        pp[0]=v0.x; pp[1]=v0.y; pp[2]=v1.x; pp[3]=v1.y;
        pp[4]=v2.x; pp[5]=v2.y; pp[6]=v3.x; pp[7]=v3.y;
        __syncthreads();
        if(tid<256){
            int b = tid>>5, hhl = tid&31;
            int h = hbase + hhl;
            float dr=br, dz=bz, dn=bn;
            #pragma unroll
            for(int q=0;q<4;q++){
                dr += part[(((0*32+hhl)*4)+q)*9 + b];
                dz += part[(((1*32+hhl)*4)+q)*9 + b];
                dn += part[(((2*32+hhl)*4)+q)*9 + b];
            }
            long gbase = (long)(t*BB + b0+b)*768;
            float gr=g_gi[gbase+h], gz=g_gi[gbase+256+h], gn=g_gi[gbase+512+h];
            float r_ = sigm_(gr+dr);
            float u  = sigm_(gz+dz);
            float nn = tanhf(gn + r_*dn);
            float hp_ = hT[h*8+b];
            float hnw = (1.f-u)*nn + u*hp_;
            g_hs[((long)t*BB + b0+b)*HH + h] = hnw;
        }
        __syncthreads();
        if(tid==0){
            __threadfence();
            atomicAdd(&g_gcnt[bg], 1);
            int target = 8*(t+1);
            while(*cnt < target){}
            __threadfence();
        }
        __syncthreads();
        for(int e=tid;e<8*HH;e+=384){ int i=e>>8, k=e&255;
            hT[k*8+i]=g_hs[((long)t*BB + b0+i)*HH + k]; }
    }
}

// ---------------- ctx ----------------
__global__ void ctx_kernel(const float* __restrict__ enc_b){
    __shared__ float hT[HH*4];
    int tid=threadIdx.x;
    int row0=blockIdx.x*4;
    for(int e=tid;e<4*HH;e+=256){int i=e>>8,k=e&255; hT[k*4+i]=g_hs[(row0+i)*HH+k];}
    __syncthreads();
    int i=tid>>6, c=tid&63;
    float acc=enc_b[c];
    #pragma unroll 4
    for(int k=0;k<HH;k++) acc = fmaf(hT[k*4+i], g_encWt[k*CC+c], acc);
    int rid=row0+i; int tr=rid>>8, b=rid&255;
    g_ctx[((TT-1-tr)*BB + b)*CC + c] = acc;
}

// ---------------- euler hidden layer: non-dup float2 weights, distance-8 ring ----------------
// 512 threads: cg=tid&127 -> cols 2cg,2cg+1 ; rq=tid>>7 (0..3) -> rows 8rq..8rq+7
template<int K, bool DOSP>
__device__ __forceinline__ void layerN(const float* __restrict__ Wn,
                                       const float* __restrict__ bias,
                                       const float* in_s, float* out_s,
                                       int cg, int rq){
    static_assert(K % 8 == 0, "K%8");
    int n0 = cg*2;
    int r0 = rq*8;
    float2 bb = *(const float2*)&bias[n0];
    ull a00=pack2(bb.x,bb.x), a01=a00, a02=a00, a03=a00;
    ull a10=pack2(bb.y,bb.y), a11=a10, a12=a10, a13=a10;
    const float2* Wp = (const float2*)&Wn[n0];     // stride HH floats = 128 float2 per c
    float2 wbuf[8];
    #pragma unroll
    for(int j=0;j<8;j++) wbuf[j] = __ldg(&Wp[(long)j*128]);
    #pragma unroll 1
    for(int cb=0; cb<K-8; cb+=8){
        #pragma unroll
        for(int j=0;j<8;j++){
            float2 w = wbuf[j];
            wbuf[j] = __ldg(&Wp[(long)(cb+8+j)*128]);
            ull wx = pack2(w.x,w.x), wy = pack2(w.y,w.y);
            const float* ip = &in_s[(cb+j)*ESTR + r0];
            ulonglong2 P0 = *(const ulonglong2*)(ip);
            ulonglong2 P1 = *(const ulonglong2*)(ip+4);
            a00=fma2(P0.x,wx,a00); a01=fma2(P0.y,wx,a01);
            a02=fma2(P1.x,wx,a02); a03=fma2(P1.y,wx,a03);
            a10=fma2(P0.x,wy,a10); a11=fma2(P0.y,wy,a11);
            a12=fma2(P1.x,wy,a12); a13=fma2(P1.y,wy,a13);
        }
    }
    #pragma unroll
    for(int j=0;j<8;j++){
        float2 w = wbuf[j];
        ull wx = pack2(w.x,w.x), wy = pack2(w.y,w.y);
        const float* ip = &in_s[(K-8+j)*ESTR + r0];
        ulonglong2 P0 = *(const ulonglong2*)(ip);
        ulonglong2 P1 = *(const ulonglong2*)(ip+4);
        a00=fma2(P0.x,wx,a00); a01=fma2(P0.y,wx,a01);
        a02=fma2(P1.x,wx,a02); a03=fma2(P1.y,wx,a03);
        a10=fma2(P0.x,wy,a10); a11=fma2(P0.y,wy,a11);
        a12=fma2(P1.x,wy,a12); a13=fma2(P1.y,wy,a13);
    }
    float2 v0,v1,v2,v3;
    float4 o;
    float* op = &out_s[n0*ESTR + r0];
    v0=unpack2(a00); v1=unpack2(a01);
    o.x = DOSP?splus_(v0.x):v0.x; o.y = DOSP?splus_(v0.y):v0.y;
    o.z = DOSP?splus_(v1.x):v1.x; o.w = DOSP?splus_(v1.y):v1.y;
    *(float4*)op = o;
    v2=unpack2(a02); v3=unpack2(a03);
    o.x = DOSP?splus_(v2.x):v2.x; o.y = DOSP?splus_(v2.y):v2.y;
    o.z = DOSP?splus_(v3.x):v3.x; o.w = DOSP?splus_(v3.y):v3.y;
    *(float4*)(op+4) = o;
    op = &out_s[(n0+1)*ESTR + r0];
    v0=unpack2(a10); v1=unpack2(a11);
    o.x = DOSP?splus_(v0.x):v0.x; o.y = DOSP?splus_(v0.y):v0.y;
    o.z = DOSP?splus_(v1.x):v1.x; o.w = DOSP?splus_(v1.y):v1.y;
    *(float4*)op = o;
    v2=unpack2(a12); v3=unpack2(a13);
    o.x = DOSP?splus_(v2.x):v2.x; o.y = DOSP?splus_(v2.y):v2.y;
    o.z = DOSP?splus_(v3.x):v3.x; o.w = DOSP?splus_(v3.y):v3.y;
    *(float4*)(op+4) = o;
}

// ---------------- output layer: W3 global k-major (coalesced, L1-resident) ----------------
__device__ __forceinline__ void outLayerG(const float* __restrict__ W3t,
        const float* __restrict__ bias, const float* in_s,
        int l, int rp, float& o0, float& o1){
    float b = __ldg(&bias[l]);
    ull acc0 = pack2(b,b), acc1 = 0ull;
    int r2 = 2*rp;
    #pragma unroll 8
    for(int kk=0;kk<HH;kk+=2){
        float w0 = __ldg(&W3t[kk*LL + l]);
        float w1 = __ldg(&W3t[(kk+1)*LL + l]);
        ull p0 = *(const ull*)&in_s[kk*ESTR + r2];
        ull p1 = *(const ull*)&in_s[(kk+1)*ESTR + r2];
        acc0 = fma2(p0, pack2(w0,w0), acc0);
        acc1 = fma2(p1, pack2(w1,w1), acc1);
    }
    float2 va = unpack2(acc0), vb = unpack2(acc1);
    o0 = va.x + vb.x; o1 = va.y + vb.y;
}

#define EULER_SMEM_FLOATS (96*ESTR + 2*HH*ESTR)
#define EULER_SMEM_BYTES  (EULER_SMEM_FLOATS*4)

// ---------------- ALL Euler steps + fused z0/KL. 128 blocks x 512 thr, 1/SM ----------------
__global__ __launch_bounds__(ETHR,1) void euler_all_kernel(
        float* __restrict__ out, const float* __restrict__ dW,
        const float* __restrict__ eps0, const float* __restrict__ qz0_W,
        const float* __restrict__ qz0_b, const float* __restrict__ pz0_mean,
        const float* __restrict__ pz0_logstd,
        const float* __restrict__ fb1,const float* __restrict__ fb2,const float* __restrict__ fb3,
        const float* __restrict__ hb1,const float* __restrict__ hb2,const float* __restrict__ hb3){
    extern __shared__ float sm[];
    float* IN  = sm;                    // 96*ESTR
    float* A1  = IN  + 96*ESTR;         // 256*ESTR
    float* A2  = A1  + HH*ESTR;         // 256*ESTR
    int tid = threadIdx.x;
    int cg = tid & 127, rq = tid >> 7;       // 0..3
    int l  = tid & 31,  rp = tid >> 5;       // 0..15
    int row0 = blockIdx.x * ERPB;            // 128 blocks
    float* zs = out+1;
    int rid0 = row0 + 2*rp, rid1 = rid0 + 1;
    float lq0 = 0.f, lq1 = 0.f;

    // ---- fused z0 ----
    {
        float* CTX0 = A1;                  // [r][cc] 32*64
        float* QS   = A2;                  // [r][c]  32*64
        for(int e=tid;e<ERPB*CC;e+=ETHR){ int r=e>>6, c=e&63;
            int b=(row0+r)&255;
            CTX0[r*64+c] = g_ctx[b*CC + c]; }
        __syncthreads();
        for(int e=tid;e<ERPB*CC;e+=ETHR){ int r=e>>6, c=e&63;
            float acc = qz0_b[c];
            const float* wrow = &qz0_W[c*CC];
            const float* crow = &CTX0[r*64];
            #pragma unroll 4
            for(int cc=0;cc<CC;cc++) acc = fmaf(crow[cc], wrow[cc], acc);
            QS[r*64+c] = acc; }
        __syncthreads();
        #pragma unroll
        for(int rr=0;rr<2;rr++){
            int r = 2*rp+rr; int rid = row0+r;
            float qm = QS[r*64+l], ql = QS[r*64+32+l];
            float val = qm + __expf(ql)*eps0[(long)rid*LL + l];
            IN[l*ESTR+r] = val;
            zs[(long)rid*TT*LL + l] = val;
        }
        if(row0 < BB){
            float kls = 0.f;
            #pragma unroll
            for(int rr=0;rr<2;rr++){
                int r = 2*rp+rr;
                float qm = QS[r*64+l], ql = QS[r*64+32+l];
                float pm = pz0_mean[l], pl = pz0_logstd[l];
                kls += pl - ql + (__expf(2.f*ql) + (qm-pm)*(qm-pm))/(2.f*__expf(2.f*pl)) - 0.5f;
            }
            #pragma unroll
            for(int off=16;off;off>>=1) kls += __shfl_down_sync(0xffffffffu, kls, off);
            if(l==0) atomicAdd(&g_acc[1], (double)kls);
        }
        __syncthreads();
    }

    const float* tabl = &g_tabv[l*TSTRIDE];

    for(int k=0;k<TT-1;k++){
        for(int e=tid;e<ERPB*CC;e+=ETHR){ int r=e>>6, c=e&63; int b=(row0+r)&255;
            IN[(32+c)*ESTR+r]=g_ctx[((k+1)*BB+b)*CC+c]; }
        __syncthreads();

        float zl0 = IN[l*ESTR + 2*rp], zl1 = IN[l*ESTR + 2*rp+1];
        float t0 = fminf(fmaxf(fmaf(zl0, INVDZ, ZOFF), 0.f), (float)(NPT-2));
        float t1 = fminf(fmaxf(fmaf(zl1, INVDZ, ZOFF), 0.f), (float)(NPT-2));
        int i0 = (int)t0, i1 = (int)t1;
        float va0=__ldg(&tabl[i0]), vb0=__ldg(&tabl[i0+1]);
        float va1=__ldg(&tabl[i1]), vb1=__ldg(&tabl[i1+1]);
        float gv0 = fmaf(t0-(float)i0, vb0-va0, va0);
        float gv1 = fmaf(t1-(float)i1, vb1-va1, va1);
        float dw0 = __ldg(&dW[((long)k*SB + rid0)*LL + l]);
        float dw1 = __ldg(&dW[((long)k*SB + rid1)*LL + l]);

        layerN<96,true>(g_fW1n, fb1, IN, A1, cg, rq);  __syncthreads();
        layerN<HH,true>(g_fW2n, fb2, A1, A2, cg, rq);  __syncthreads();
        float fv0, fv1;
        outLayerG(g_fW3t, fb3, A2, l, rp, fv0, fv1);
        layerN<LL,true>(g_hW1n, hb1, IN, A1, cg, rq);  __syncthreads();
        layerN<HH,true>(g_hW2n, hb2, A1, A2, cg, rq);  __syncthreads();
        float hv0, hv1;
        outLayerG(g_hW3t, hb3, A2, l, rp, hv0, hv1);

        float u0 = __fdividef(fv0-hv0, gv0);
        float u1 = __fdividef(fv1-hv1, gv1);
        float zn0 = zl0 + fv0*DTV + gv0*(SQDT*dw0);
        float zn1 = zl1 + fv1*DTV + gv1*(SQDT*dw1);
        *(float2*)&IN[l*ESTR + 2*rp] = make_float2(zn0, zn1);
        zs[((long)rid0*TT + k+1)*LL + l] = zn0;
        zs[((long)rid1*TT + k+1)*LL + l] = zn1;
        float s0=u0*u0, s1=u1*u1;
        #pragma unroll
        for(int off=16;off;off>>=1){
            s0 += __shfl_down_sync(0xffffffffu, s0, off);
            s1 += __shfl_down_sync(0xffffffffu, s1, off);
        }
        if(l==0){ lq0 += 0.5f*s0*DTV; lq1 += 0.5f*s1*DTV; }
        __syncthreads();
    }
    if(l==0){ g_logqp[rid0]=lq0; g_logqp[rid1]=lq1; }
}

// ---------------- Poisson readout (C column hoisted to registers) ----------------
__global__ void readout_kernel(const float* __restrict__ xs_pre, const float* __restrict__ C_out,
                               const float* __restrict__ d_out_v, const float* __restrict__ out){
    __shared__ float Cs[LL*DD];
    __shared__ float Zs[SS*LL];
    __shared__ float red[4];
    const float* zs = out+1;
    int blk=blockIdx.x; int t=blk>>8, b=blk&255;
    int d=threadIdx.x;
    for(int e=d;e<LL*DD;e+=128) Cs[e]=C_out[e];
    for(int e=d;e<SS*LL;e+=128){int s=e>>5,l=e&31;
        Zs[e]=zs[((long)(s*BB+b)*TT + t)*LL + l];}
    __syncthreads();
    float creg[LL];
    #pragma unroll
    for(int l=0;l<LL;l++) creg[l]=Cs[l*DD+d];
    float x = xs_pre[(b*TT+t)*DD+d];
    const float lut[5]={0.f,0.f,0.6931471805599453f,1.791759469228055f,3.1780538303479458f};
    int xi=(int)x;
    float lg = (xi>=0 && xi<5) ? lut[xi] : lgammaf(x+1.f);
    float base = d_out_v[d] + LOGDT;
    float acc=0.f;
    for(int s=0;s<SS;s++){
        float lr=base;
        #pragma unroll
        for(int l=0;l<LL;l++) lr = fmaf(Zs[s*LL+l], creg[l], lr);
        acc += x*lr - __expf(lr) - lg;
    }
    #pragma unroll
    for(int off=16;off;off>>=1) acc += __shfl_down_sync(0xffffffffu, acc, off);
    if((d&31)==0) red[d>>5]=acc;
    __syncthreads();
    if(d==0){
        float s=red[0]+red[1]+red[2]+red[3];
        atomicAdd(&g_acc[0], (double)s);
    }
}

// ---------------- mean / unbiased variance ----------------
__global__ void meanvar_kernel(float* __restrict__ out){
    int idx=blockIdx.x*256+threadIdx.x;
    if(idx>=BB*TT*LL) return;
    const float* zs=out+1;
    float v[SS];
    float sum=0.f;
    #pragma unroll
    for(int s=0;s<SS;s++){ v[s]=zs[(long)s*(BB*TT*LL)+idx]; sum+=v[s]; }
    float m=sum*(1.f/SS);
    float var=0.f;
    #pragma unroll
    for(int s=0;s<SS;s++){ float d=v[s]-m; var=fmaf(d,d,var); }
    var *= (1.f/(SS-1));
    out[1+(long)SS*BB*TT*LL + idx]=m;
    out[1+(long)SS*BB*TT*LL + BB*TT*LL + idx]=var;
}

// ---------------- final loss ----------------
__global__ void final_kernel(float* __restrict__ out){
    __shared__ float red[256];
    int tid=threadIdx.x;
    float s=0.f;
    for(int i=tid;i<SB;i+=256) s+=g_logqp[i];
    red[tid]=s; __syncthreads();
    for(int st=128;st;st>>=1){ if(tid<st) red[tid]+=red[tid+st]; __syncthreads(); }
    if(tid==0){
        float log_pxs   = (float)(g_acc[0] / (double)(SS*BB));
        float logqp0    = (float)(g_acc[1] / (double)BB);
        float path      = red[0] / (float)(SS*BB);
        out[0] = -log_pxs + logqp0 + path;
    }
}

// ---------------- launch ----------------
extern "C" void kernel_launch(void* const* d_in, const int* in_sizes, int n_in,
                              void* d_out, int out_size){
    const float* xs_pre   =(const float*)d_in[0];
    const float* eps0     =(const float*)d_in[1];
    const float* dW       =(const float*)d_in[2];
    const float* gru_Wih  =(const float*)d_in[3];
    const float* gru_Whh  =(const float*)d_in[4];
    const float* gru_bih  =(const float*)d_in[5];
    const float* gru_bhh  =(const float*)d_in[6];
    const float* enc_W    =(const float*)d_in[7];
    const float* enc_b    =(const float*)d_in[8];
    const float* qz0_W    =(const float*)d_in[9];
    const float* qz0_b    =(const float*)d_in[10];
    const float* fW1      =(const float*)d_in[11];
    const float* fb1      =(const float*)d_in[12];
    const float* fW2      =(const float*)d_in[13];
    const float* fb2      =(const float*)d_in[14];
    const float* fW3      =(const float*)d_in[15];
    const float* fb3      =(const float*)d_in[16];
    const float* hW1      =(const float*)d_in[17];
    const float* hb1      =(const float*)d_in[18];
    const float* hW2      =(const float*)d_in[19];
    const float* hb2      =(const float*)d_in[20];
    const float* hW3      =(const float*)d_in[21];
    const float* hb3      =(const float*)d_in[22];
    const float* gW1      =(const float*)d_in[23];
    const float* gb1      =(const float*)d_in[24];
    const float* gW2      =(const float*)d_in[25];
    const float* gb2      =(const float*)d_in[26];
    const float* pz0_mean =(const float*)d_in[27];
    const float* pz0_logstd=(const float*)d_in[28];
    const float* C_out    =(const float*)d_in[29];
    const float* d_out_v  =(const float*)d_in[30];
    float* out=(float*)d_out;

    static int smem_set = 0;
    if(!smem_set){
        cudaFuncSetAttribute(euler_all_kernel,
                             cudaFuncAttributeMaxDynamicSharedMemorySize, EULER_SMEM_BYTES);
        smem_set = 1;
    }

    prep_kernel<<<256,256>>>(gru_Wih,gru_Whh,fW1,fW2,fW3,hW1,hW2,hW3,enc_W);
    tabv_kernel<<<dim3((NPT+255)/256,32),256>>>(gW1,gb1,gW2,gb2);
    gi_kernel<<<4096,256>>>(xs_pre, gru_bih);
    gru_all_kernel<<<256,384>>>(gru_bhh);
    ctx_kernel<<<8192,256>>>(enc_b);
    euler_all_kernel<<<128,ETHR,EULER_SMEM_BYTES>>>(out,dW,eps0,qz0_W,qz0_b,pz0_mean,pz0_logstd,
                                                    fb1,fb2,fb3,hb1,hb2,hb3);
    readout_kernel<<<32768,128>>>(xs_pre,C_out,d_out_v,out);
    meanvar_kernel<<<4096,256>>>(out);
    final_kernel<<<1,256>>>(out);
}

// round 17
// speedup vs baseline: 1.0386x; 1.0386x over previous
#include <cuda_runtime.h>
#include <cuda_bf16.h>
#include <math.h>

#define TT 128
#define BB 256
#define DD 128
#define LL 32
#define CC 64
#define HH 256
#define SS 16
#define SB 4096   // SS*BB

#define DTV 0.02f
#define SQDT 0.14142135623730951f     // sqrt(0.02)
#define LOGDT -3.9120230054281460f    // log(0.02)

// g-table: values only, z in [-24,24], step 1/128
#define NPT 6145
#define TSTRIDE 6208
#define INVDZ 128.0f
#define ZOFF 3072.0f
#define ZLO -24.0f

// euler geometry: 256 blocks x 256 threads, 16 rows/block, 2 blocks/SM
#define ERPB 16      // rows per block
#define ESTR 20      // smem activation stride (floats; 80B = 16B-aligned rows)
#define ETHR 256

typedef unsigned long long ull;

// ---------------- device scratch ----------------
static __device__ float g_WihT[DD*768];
static __device__ float g_WhhT[HH*768];
static __device__ float g_encWt[HH*CC];
static __device__ float g_fW1n[96*HH];     // non-dup, k-major: [c*256+n]
static __device__ float g_fW2n[HH*HH];
static __device__ float g_hW1n[LL*HH];
static __device__ float g_hW2n[HH*HH];
static __device__ float2 g_fW3p[(HH/2)*LL]; // paired: [kk2*32+l] = {W3[2kk2][l], W3[2kk2+1][l]}
static __device__ float2 g_hW3p[(HH/2)*LL];
static __device__ float g_gi[TT*BB*768];
static __device__ float g_hs[TT*BB*HH];
static __device__ float g_ctx[TT*BB*CC];
static __device__ float g_logqp[SB];
static __device__ double g_acc[2];
static __device__ int    g_gcnt[32];
static __device__ float  g_tabv[32*TSTRIDE];

__device__ __forceinline__ float sigm_(float x){ return 1.f/(1.f+__expf(-x)); }
__device__ __forceinline__ float splus_(float x){
    return fmaxf(x,0.f) + __logf(1.f+__expf(-fabsf(x)));
}
__device__ __forceinline__ ull pack2(float x, float y){
    ull r; asm("mov.b64 %0, {%1,%2};" : "=l"(r) : "f"(x), "f"(y)); return r;
}
__device__ __forceinline__ ull fma2(ull a, ull b, ull c){
    ull d; asm("fma.rn.f32x2 %0, %1, %2, %3;" : "=l"(d) : "l"(a), "l"(b), "l"(c)); return d;
}
__device__ __forceinline__ float2 unpack2(ull v){
    float2 f; asm("mov.b64 {%0,%1}, %2;" : "=f"(f.x), "=f"(f.y) : "l"(v)); return f;
}

// ---------------- prep ----------------
__global__ void prep_kernel(const float* __restrict__ Wih, const float* __restrict__ Whh,
                            const float* __restrict__ fW1, const float* __restrict__ fW2,
                            const float* __restrict__ fW3, const float* __restrict__ hW1,
                            const float* __restrict__ hW2, const float* __restrict__ hW3,
                            const float* __restrict__ encW){
    int i = blockIdx.x*blockDim.x + threadIdx.x;
    int nth = gridDim.x*blockDim.x;
    for (int k=i;k<SB;k+=nth)    g_logqp[k]=0.f;
    if (i<2) g_acc[i]=0.0;
    if (i<32) g_gcnt[i]=0;
    for (int k=i;k<768*DD;k+=nth){int n=k/DD,d=k%DD; g_WihT[d*768+n]=Wih[k];}
    for (int k=i;k<768*HH;k+=nth){int n=k/HH,d=k%HH; g_WhhT[d*768+n]=Whh[k];}
    for (int k=i;k<CC*HH;k+=nth){int c2=k/HH,kk=k%HH;g_encWt[kk*CC+c2]=encW[k];}
    for (int k=i;k<HH*96;k+=nth){int n=k/96,c=k%96;  g_fW1n[c*HH+n]=fW1[k];}
    for (int k=i;k<HH*HH;k+=nth){int n=k/HH,c=k%HH;  g_fW2n[c*HH+n]=fW2[k];}
    for (int k=i;k<HH*LL;k+=nth){int n=k/LL,c=k%LL;  g_hW1n[c*HH+n]=hW1[k];}
    for (int k=i;k<HH*HH;k+=nth){int n=k/HH,c=k%HH;  g_hW2n[c*HH+n]=hW2[k];}
    // W3 paired: input fW3[l*HH + kk]
    for (int k=i;k<LL*(HH/2);k+=nth){int l=k/(HH/2),kk2=k%(HH/2);
        g_fW3p[kk2*LL+l]=make_float2(fW3[l*HH+2*kk2], fW3[l*HH+2*kk2+1]);
        g_hW3p[kk2*LL+l]=make_float2(hW3[l*HH+2*kk2], hW3[l*HH+2*kk2+1]);}
}

// ---------------- g-table build ----------------
__global__ void tabv_kernel(const float* __restrict__ gW1,const float* __restrict__ gb1,
                            const float* __restrict__ gW2,const float* __restrict__ gb2){
    __shared__ float w1[HH], b1[HH], w2[HH];
    int l = blockIdx.y;
    int tid = threadIdx.x;
    if(tid<HH){ w1[tid]=gW1[l*HH+tid]; b1[tid]=gb1[l*HH+tid]; w2[tid]=gW2[l*HH+tid]; }
    __syncthreads();
    int j = blockIdx.x*256 + tid;
    if(j>=NPT) return;
    float z = ZLO + (float)j*(1.0f/INVDZ);
    float acc=0.f;
    #pragma unroll 4
    for(int h=0;h<HH;h++){
        float t = fmaf(z, w1[h], b1[h]);
        acc = fmaf(splus_(t), w2[h], acc);
    }
    g_tabv[l*TSTRIDE+j] = 1.f/(1.f+__expf(-(acc+gb2[l]))) + 0.01f;
}

// ---------------- gi = xs_rev @ WihT + bih ----------------
__global__ void gi_kernel(const float* __restrict__ xs_pre, const float* __restrict__ bih){
    __shared__ float xT[DD*8];
    int tid = threadIdx.x;
    int row0 = blockIdx.x*8;
    for (int e=tid; e<8*DD; e+=256){
        int i=e>>7, k=e&127;
        int rid=row0+i; int t=rid>>8, b=rid&255;
        xT[k*8+i] = xs_pre[(b*TT + (TT-1-t))*DD + k];
    }
    __syncthreads();
    int n0=tid, n1=tid+256, n2=tid+512;
    float a0[8],a1[8],a2[8];
    float b0=bih[n0], b1=bih[n1], b2=bih[n2];
    #pragma unroll
    for(int i=0;i<8;i++){a0[i]=b0;a1[i]=b1;a2[i]=b2;}
    #pragma unroll 2
    for(int k=0;k<DD;k++){
        float w0=g_WihT[k*768+n0], w1=g_WihT[k*768+n1], w2=g_WihT[k*768+n2];
        float4 xa=*(const float4*)&xT[k*8], xb=*(const float4*)&xT[k*8+4];
        float xv[8]={xa.x,xa.y,xa.z,xa.w,xb.x,xb.y,xb.z,xb.w};
        #pragma unroll
        for(int i=0;i<8;i++){a0[i]=fmaf(xv[i],w0,a0[i]);a1[i]=fmaf(xv[i],w1,a1[i]);a2[i]=fmaf(xv[i],w2,a2[i]);}
    }
    for(int i=0;i<8;i++){
        int rid=row0+i;
        g_gi[rid*768+n0]=a0[i]; g_gi[rid*768+n1]=a1[i]; g_gi[rid*768+n2]=a2[i];
    }
}

// ---------------- persistent GRU ----------------
__global__ __launch_bounds__(384,2) void gru_all_kernel(const float* __restrict__ bhh){
    __shared__ float hT[HH*8];
    __shared__ float part[96*4*9];
    int tid = threadIdx.x;
    int bg = blockIdx.x>>3, hg = blockIdx.x&7;
    int b0 = bg*8, hbase = hg*32;
    for(int e=tid;e<8*HH;e+=384) hT[e]=0.f;

    int c  = tid%96;
    int kp = tid/96;
    int gate = c>>5;
    int n = gate*256 + hbase + (c&31);
    int k0 = kp*64;
    const float* wcol = &g_WhhT[(long)k0*768 + n];
    float br=bhh[hbase+(tid&31)], bz=bhh[256+hbase+(tid&31)], bn=bhh[512+hbase+(tid&31)];

    volatile int* cnt = (volatile int*)&g_gcnt[bg];

    for(int t=0;t<TT;t++){
        __syncthreads();
        ull acc0=0ull, acc1=0ull, acc2=0ull, acc3=0ull;
        #pragma unroll 4
        for(int kk=0;kk<64;kk++){
            float w = __ldg(&wcol[(long)kk*768]);
            ull wp = pack2(w,w);
            const ull* hp = (const ull*)&hT[(k0+kk)*8];
            acc0=fma2(hp[0],wp,acc0); acc1=fma2(hp[1],wp,acc1);
            acc2=fma2(hp[2],wp,acc2); acc3=fma2(hp[3],wp,acc3);
        }
        float* pp = &part[(c*4+kp)*9];
        float2 v0=unpack2(acc0), v1=unpack2(acc1), v2=unpack2(acc2), v3=unpack2(acc3);
        pp[0]=v0.x; pp[1]=v0.y; pp[2]=v1.x; pp[3]=v1.y;
        pp[4]=v2.x; pp[5]=v2.y; pp[6]=v3.x; pp[7]=v3.y;
        __syncthreads();
        if(tid<256){
            int b = tid>>5, hhl = tid&31;
            int h = hbase + hhl;
            float dr=br, dz=bz, dn=bn;
            #pragma unroll
            for(int q=0;q<4;q++){
                dr += part[(((0*32+hhl)*4)+q)*9 + b];
                dz += part[(((1*32+hhl)*4)+q)*9 + b];
                dn += part[(((2*32+hhl)*4)+q)*9 + b];
            }
            long gbase = (long)(t*BB + b0+b)*768;
            float gr=g_gi[gbase+h], gz=g_gi[gbase+256+h], gn=g_gi[gbase+512+h];
            float r_ = sigm_(gr+dr);
            float u  = sigm_(gz+dz);
            float nn = tanhf(gn + r_*dn);
            float hp_ = hT[h*8+b];
            float hnw = (1.f-u)*nn + u*hp_;
            g_hs[((long)t*BB + b0+b)*HH + h] = hnw;
        }
        __syncthreads();
        if(tid==0){
            __threadfence();
            atomicAdd(&g_gcnt[bg], 1);
            int target = 8*(t+1);
            while(*cnt < target){}
            __threadfence();
        }
        __syncthreads();
        for(int e=tid;e<8*HH;e+=384){ int i=e>>8, k=e&255;
            hT[k*8+i]=g_hs[((long)t*BB + b0+i)*HH + k]; }
    }
}

// ---------------- ctx ----------------
__global__ void ctx_kernel(const float* __restrict__ enc_b){
    __shared__ float hT[HH*4];
    int tid=threadIdx.x;
    int row0=blockIdx.x*4;
    for(int e=tid;e<4*HH;e+=256){int i=e>>8,k=e&255; hT[k*4+i]=g_hs[(row0+i)*HH+k];}
    __syncthreads();
    int i=tid>>6, c=tid&63;
    float acc=enc_b[c];
    #pragma unroll 4
    for(int k=0;k<HH;k++) acc = fmaf(hT[k*4+i], g_encWt[k*CC+c], acc);
    int rid=row0+i; int tr=rid>>8, b=rid&255;
    g_ctx[((TT-1-tr)*BB + b)*CC + c] = acc;
}

// ---------------- euler hidden layer: non-dup float2 weights, distance-8 ring ----------------
// 256 threads: cg=tid&127 -> cols 2cg,2cg+1 ; rq=tid>>7 (0..1) -> rows 8rq..8rq+7
template<int K, bool DOSP>
__device__ __forceinline__ void layerN(const float* __restrict__ Wn,
                                       const float* __restrict__ bias,
                                       const float* in_s, float* out_s,
                                       int cg, int rq){
    static_assert(K % 8 == 0, "K%8");
    int n0 = cg*2;
    int r0 = rq*8;
    float2 bb = *(const float2*)&bias[n0];
    ull a00=pack2(bb.x,bb.x), a01=a00, a02=a00, a03=a00;
    ull a10=pack2(bb.y,bb.y), a11=a10, a12=a10, a13=a10;
    const float2* Wp = (const float2*)&Wn[n0];     // stride HH floats = 128 float2 per c
    float2 wbuf[8];
    #pragma unroll
    for(int j=0;j<8;j++) wbuf[j] = __ldg(&Wp[(long)j*128]);
    #pragma unroll 1
    for(int cb=0; cb<K-8; cb+=8){
        #pragma unroll
        for(int j=0;j<8;j++){
            float2 w = wbuf[j];
            wbuf[j] = __ldg(&Wp[(long)(cb+8+j)*128]);
            ull wx = pack2(w.x,w.x), wy = pack2(w.y,w.y);
            const float* ip = &in_s[(cb+j)*ESTR + r0];
            ulonglong2 P0 = *(const ulonglong2*)(ip);
            ulonglong2 P1 = *(const ulonglong2*)(ip+4);
            a00=fma2(P0.x,wx,a00); a01=fma2(P0.y,wx,a01);
            a02=fma2(P1.x,wx,a02); a03=fma2(P1.y,wx,a03);
            a10=fma2(P0.x,wy,a10); a11=fma2(P0.y,wy,a11);
            a12=fma2(P1.x,wy,a12); a13=fma2(P1.y,wy,a13);
        }
    }
    #pragma unroll
    for(int j=0;j<8;j++){
        float2 w = wbuf[j];
        ull wx = pack2(w.x,w.x), wy = pack2(w.y,w.y);
        const float* ip = &in_s[(K-8+j)*ESTR + r0];
        ulonglong2 P0 = *(const ulonglong2*)(ip);
        ulonglong2 P1 = *(const ulonglong2*)(ip+4);
        a00=fma2(P0.x,wx,a00); a01=fma2(P0.y,wx,a01);
        a02=fma2(P1.x,wx,a02); a03=fma2(P1.y,wx,a03);
        a10=fma2(P0.x,wy,a10); a11=fma2(P0.y,wy,a11);
        a12=fma2(P1.x,wy,a12); a13=fma2(P1.y,wy,a13);
    }
    float2 v0,v1,v2,v3;
    float4 o;
    float* op = &out_s[n0*ESTR + r0];
    v0=unpack2(a00); v1=unpack2(a01);
    o.x = DOSP?splus_(v0.x):v0.x; o.y = DOSP?splus_(v0.y):v0.y;
    o.z = DOSP?splus_(v1.x):v1.x; o.w = DOSP?splus_(v1.y):v1.y;
    *(float4*)op = o;
    v2=unpack2(a02); v3=unpack2(a03);
    o.x = DOSP?splus_(v2.x):v2.x; o.y = DOSP?splus_(v2.y):v2.y;
    o.z = DOSP?splus_(v3.x):v3.x; o.w = DOSP?splus_(v3.y):v3.y;
    *(float4*)(op+4) = o;
    op = &out_s[(n0+1)*ESTR + r0];
    v0=unpack2(a10); v1=unpack2(a11);
    o.x = DOSP?splus_(v0.x):v0.x; o.y = DOSP?splus_(v0.y):v0.y;
    o.z = DOSP?splus_(v1.x):v1.x; o.w = DOSP?splus_(v1.y):v1.y;
    *(float4*)op = o;
    v2=unpack2(a12); v3=unpack2(a13);
    o.x = DOSP?splus_(v2.x):v2.x; o.y = DOSP?splus_(v2.y):v2.y;
    o.z = DOSP?splus_(v3.x):v3.x; o.w = DOSP?splus_(v3.y):v3.y;
    *(float4*)(op+4) = o;
}

// ---------------- output layer: paired W3 (LDG.64, coalesced, L1-resident) ----------------
__device__ __forceinline__ void outLayerP(const float2* __restrict__ W3p,
        const float* __restrict__ bias, const float* in_s,
        int l, int rp, float& o0, float& o1){
    float b = __ldg(&bias[l]);
    ull acc0 = pack2(b,b), acc1 = 0ull;
    int r2 = 2*rp;
    #pragma unroll 8
    for(int kk2=0;kk2<HH/2;kk2++){
        float2 w = __ldg(&W3p[kk2*LL + l]);
        ull p0 = *(const ull*)&in_s[(2*kk2  )*ESTR + r2];
        ull p1 = *(const ull*)&in_s[(2*kk2+1)*ESTR + r2];
        acc0 = fma2(p0, pack2(w.x,w.x), acc0);
        acc1 = fma2(p1, pack2(w.y,w.y), acc1);
    }
    float2 va = unpack2(acc0), vb = unpack2(acc1);
    o0 = va.x + vb.x; o1 = va.y + vb.y;
}

// smem: IN(96) + A1F(256) + A1H(256) + A2F(256) + A2H(256) rows of ESTR floats
#define EULER_SMEM_FLOATS ((96 + 4*HH)*ESTR)
#define EULER_SMEM_BYTES  (EULER_SMEM_FLOATS*4)

// ---------------- ALL Euler steps + fused z0/KL. 256 blocks x 256 thr, 2/SM, 4 barriers/step ----------------
__global__ __launch_bounds__(ETHR,2) void euler_all_kernel(
        float* __restrict__ out, const float* __restrict__ dW,
        const float* __restrict__ eps0, const float* __restrict__ qz0_W,
        const float* __restrict__ qz0_b, const float* __restrict__ pz0_mean,
        const float* __restrict__ pz0_logstd,
        const float* __restrict__ fb1,const float* __restrict__ fb2,const float* __restrict__ fb3,
        const float* __restrict__ hb1,const float* __restrict__ hb2,const float* __restrict__ hb3){
    extern __shared__ float sm[];
    float* IN  = sm;                    // 96*ESTR
    float* A1F = IN  + 96*ESTR;         // 256*ESTR
    float* A1H = A1F + HH*ESTR;
    float* A2F = A1H + HH*ESTR;
    float* A2H = A2F + HH*ESTR;
    int tid = threadIdx.x;
    int cg = tid & 127, rq = tid >> 7;       // 0..1
    int l  = tid & 31,  rp = tid >> 5;       // 0..7
    int row0 = blockIdx.x * ERPB;            // 256 blocks
    float* zs = out+1;
    int rid0 = row0 + 2*rp, rid1 = rid0 + 1;
    float lq0 = 0.f, lq1 = 0.f;

    // ---- fused z0 ----
    {
        float* CTX0 = A1F;                 // [r][cc] 16*64
        float* QS   = A2F;                 // [r][c]  16*64
        for(int e=tid;e<ERPB*CC;e+=ETHR){ int r=e>>6, c=e&63;
            int b=(row0+r)&255;
            CTX0[r*64+c] = g_ctx[b*CC + c]; }
        __syncthreads();
        for(int e=tid;e<ERPB*CC;e+=ETHR){ int r=e>>6, c=e&63;
            float acc = qz0_b[c];
            const float* wrow = &qz0_W[c*CC];
            const float* crow = &CTX0[r*64];
            #pragma unroll 4
            for(int cc=0;cc<CC;cc++) acc = fmaf(crow[cc], wrow[cc], acc);
            QS[r*64+c] = acc; }
        __syncthreads();
        #pragma unroll
        for(int rr=0;rr<2;rr++){
            int r = 2*rp+rr; int rid = row0+r;
            float qm = QS[r*64+l], ql = QS[r*64+32+l];
            float val = qm + __expf(ql)*eps0[(long)rid*LL + l];
            IN[l*ESTR+r] = val;
            zs[(long)rid*TT*LL + l] = val;
        }
        if(row0 < BB){
            float kls = 0.f;
            #pragma unroll
            for(int rr=0;rr<2;rr++){
                int r = 2*rp+rr;
                float qm = QS[r*64+l], ql = QS[r*64+32+l];
                float pm = pz0_mean[l], pl = pz0_logstd[l];
                kls += pl - ql + (__expf(2.f*ql) + (qm-pm)*(qm-pm))/(2.f*__expf(2.f*pl)) - 0.5f;
            }
            #pragma unroll
            for(int off=16;off;off>>=1) kls += __shfl_down_sync(0xffffffffu, kls, off);
            if(l==0) atomicAdd(&g_acc[1], (double)kls);
        }
        __syncthreads();
    }

    const float* tabl = &g_tabv[l*TSTRIDE];

    for(int k=0;k<TT-1;k++){
        for(int e=tid;e<ERPB*CC;e+=ETHR){ int r=e>>6, c=e&63; int b=(row0+r)&255;
            IN[(32+c)*ESTR+r]=g_ctx[((k+1)*BB+b)*CC+c]; }
        __syncthreads();                                  // barrier 1

        float zl0 = IN[l*ESTR + 2*rp], zl1 = IN[l*ESTR + 2*rp+1];
        float t0 = fminf(fmaxf(fmaf(zl0, INVDZ, ZOFF), 0.f), (float)(NPT-2));
        float t1 = fminf(fmaxf(fmaf(zl1, INVDZ, ZOFF), 0.f), (float)(NPT-2));
        int i0 = (int)t0, i1 = (int)t1;
        float va0=__ldg(&tabl[i0]), vb0=__ldg(&tabl[i0+1]);
        float va1=__ldg(&tabl[i1]), vb1=__ldg(&tabl[i1+1]);
        float gv0 = fmaf(t0-(float)i0, vb0-va0, va0);
        float gv1 = fmaf(t1-(float)i1, vb1-va1, va1);
        float dw0 = __ldg(&dW[((long)k*SB + rid0)*LL + l]);
        float dw1 = __ldg(&dW[((long)k*SB + rid1)*LL + l]);

        layerN<96,true>(g_fW1n, fb1, IN, A1F, cg, rq);
        layerN<LL,true>(g_hW1n, hb1, IN, A1H, cg, rq);
        __syncthreads();                                  // barrier 2
        layerN<HH,true>(g_fW2n, fb2, A1F, A2F, cg, rq);
        layerN<HH,true>(g_hW2n, hb2, A1H, A2H, cg, rq);
        __syncthreads();                                  // barrier 3
        float fv0, fv1, hv0, hv1;
        outLayerP(g_fW3p, fb3, A2F, l, rp, fv0, fv1);
        outLayerP(g_hW3p, hb3, A2H, l, rp, hv0, hv1);

        float u0 = __fdividef(fv0-hv0, gv0);
        float u1 = __fdividef(fv1-hv1, gv1);
        float zn0 = zl0 + fv0*DTV + gv0*(SQDT*dw0);
        float zn1 = zl1 + fv1*DTV + gv1*(SQDT*dw1);
        *(float2*)&IN[l*ESTR + 2*rp] = make_float2(zn0, zn1);
        zs[((long)rid0*TT + k+1)*LL + l] = zn0;
        zs[((long)rid1*TT + k+1)*LL + l] = zn1;
        float s0=u0*u0, s1=u1*u1;
        #pragma unroll
        for(int off=16;off;off>>=1){
            s0 += __shfl_down_sync(0xffffffffu, s0, off);
            s1 += __shfl_down_sync(0xffffffffu, s1, off);
        }
        if(l==0){ lq0 += 0.5f*s0*DTV; lq1 += 0.5f*s1*DTV; }
        __syncthreads();                                  // barrier 4
    }
    if(l==0){ g_logqp[rid0]=lq0; g_logqp[rid1]=lq1; }
}

// ---------------- Poisson readout ----------------
__global__ void readout_kernel(const float* __restrict__ xs_pre, const float* __restrict__ C_out,
                               const float* __restrict__ d_out_v, const float* __restrict__ out){
    __shared__ float Cs[LL*DD];
    __shared__ float Zs[SS*LL];
    __shared__ float red[4];
    const float* zs = out+1;
    int blk=blockIdx.x; int t=blk>>8, b=blk&255;
    int d=threadIdx.x;
    for(int e=d;e<LL*DD;e+=128) Cs[e]=C_out[e];
    for(int e=d;e<SS*LL;e+=128){int s=e>>5,l=e&31;
        Zs[e]=zs[((long)(s*BB+b)*TT + t)*LL + l];}
    __syncthreads();
    float creg[LL];
    #pragma unroll
    for(int l=0;l<LL;l++) creg[l]=Cs[l*DD+d];
    float x = xs_pre[(b*TT+t)*DD+d];
    const float lut[5]={0.f,0.f,0.6931471805599453f,1.791759469228055f,3.1780538303479458f};
    int xi=(int)x;
    float lg = (xi>=0 && xi<5) ? lut[xi] : lgammaf(x+1.f);
    float base = d_out_v[d] + LOGDT;
    float acc=0.f;
    for(int s=0;s<SS;s++){
        float lr=base;
        #pragma unroll
        for(int l=0;l<LL;l++) lr = fmaf(Zs[s*LL+l], creg[l], lr);
        acc += x*lr - __expf(lr) - lg;
    }
    #pragma unroll
    for(int off=16;off;off>>=1) acc += __shfl_down_sync(0xffffffffu, acc, off);
    if((d&31)==0) red[d>>5]=acc;
    __syncthreads();
    if(d==0){
        float s=red[0]+red[1]+red[2]+red[3];
        atomicAdd(&g_acc[0], (double)s);
    }
}

// ---------------- mean / unbiased variance ----------------
__global__ void meanvar_kernel(float* __restrict__ out){
    int idx=blockIdx.x*256+threadIdx.x;
    if(idx>=BB*TT*LL) return;
    const float* zs=out+1;
    float v[SS];
    float sum=0.f;
    #pragma unroll
    for(int s=0;s<SS;s++){ v[s]=zs[(long)s*(BB*TT*LL)+idx]; sum+=v[s]; }
    float m=sum*(1.f/SS);
    float var=0.f;
    #pragma unroll
    for(int s=0;s<SS;s++){ float d=v[s]-m; var=fmaf(d,d,var); }
    var *= (1.f/(SS-1));
    out[1+(long)SS*BB*TT*LL + idx]=m;
    out[1+(long)SS*BB*TT*LL + BB*TT*LL + idx]=var;
}

// ---------------- final loss ----------------
__global__ void final_kernel(float* __restrict__ out){
    __shared__ float red[256];
    int tid=threadIdx.x;
    float s=0.f;
    for(int i=tid;i<SB;i+=256) s+=g_logqp[i];
    red[tid]=s; __syncthreads();
    for(int st=128;st;st>>=1){ if(tid<st) red[tid]+=red[tid+st]; __syncthreads(); }
    if(tid==0){
        float log_pxs   = (float)(g_acc[0] / (double)(SS*BB));
        float logqp0    = (float)(g_acc[1] / (double)BB);
        float path      = red[0] / (float)(SS*BB);
        out[0] = -log_pxs + logqp0 + path;
    }
}

// ---------------- launch ----------------
extern "C" void kernel_launch(void* const* d_in, const int* in_sizes, int n_in,
                              void* d_out, int out_size){
    const float* xs_pre   =(const float*)d_in[0];
    const float* eps0     =(const float*)d_in[1];
    const float* dW       =(const float*)d_in[2];
    const float* gru_Wih  =(const float*)d_in[3];
    const float* gru_Whh  =(const float*)d_in[4];
    const float* gru_bih  =(const float*)d_in[5];
    const float* gru_bhh  =(const float*)d_in[6];
    const float* enc_W    =(const float*)d_in[7];
    const float* enc_b    =(const float*)d_in[8];
    const float* qz0_W    =(const float*)d_in[9];
    const float* qz0_b    =(const float*)d_in[10];
    const float* fW1      =(const float*)d_in[11];
    const float* fb1      =(const float*)d_in[12];
    const float* fW2      =(const float*)d_in[13];
    const float* fb2      =(const float*)d_in[14];
    const float* fW3      =(const float*)d_in[15];
    const float* fb3      =(const float*)d_in[16];
    const float* hW1      =(const float*)d_in[17];
    const float* hb1      =(const float*)d_in[18];
    const float* hW2      =(const float*)d_in[19];
    const float* hb2      =(const float*)d_in[20];
    const float* hW3      =(const float*)d_in[21];
    const float* hb3      =(const float*)d_in[22];
    const float* gW1      =(const float*)d_in[23];
    const float* gb1      =(const float*)d_in[24];
    const float* gW2      =(const float*)d_in[25];
    const float* gb2      =(const float*)d_in[26];
    const float* pz0_mean =(const float*)d_in[27];
    const float* pz0_logstd=(const float*)d_in[28];
    const float* C_out    =(const float*)d_in[29];
    const float* d_out_v  =(const float*)d_in[30];
    float* out=(float*)d_out;

    static int smem_set = 0;
    if(!smem_set){
        cudaFuncSetAttribute(euler_all_kernel,
                             cudaFuncAttributeMaxDynamicSharedMemorySize, EULER_SMEM_BYTES);
        smem_set = 1;
    }

    prep_kernel<<<256,256>>>(gru_Wih,gru_Whh,fW1,fW2,fW3,hW1,hW2,hW3,enc_W);
    tabv_kernel<<<dim3((NPT+255)/256,32),256>>>(gW1,gb1,gW2,gb2);
    gi_kernel<<<4096,256>>>(xs_pre, gru_bih);
    gru_all_kernel<<<256,384>>>(gru_bhh);
    ctx_kernel<<<8192,256>>>(enc_b);
    euler_all_kernel<<<256,ETHR,EULER_SMEM_BYTES>>>(out,dW,eps0,qz0_W,qz0_b,pz0_mean,pz0_logstd,
                                                    fb1,fb2,fb3,hb1,hb2,hb3);
    readout_kernel<<<32768,128>>>(xs_pre,C_out,d_out_v,out);
    meanvar_kernel<<<4096,256>>>(out);
    final_kernel<<<1,256>>>(out);
}